// round 13
// baseline (speedup 1.0000x reference)
#include <cuda_runtime.h>
#include <cuda_bf16.h>
#include <cstdint>

// S4D kernel materialization via bf16 mma.sync (HMMA), all-fp32 setup.
//   K[h, l] = Re( sum_n S0c[h,n] * w^l ),  w = exp(dtA),  S0c = 2*C*(exp(dtA)-1)/A
// l = i + 64*j:  D[j,i] = sum_n Qr[n,j]*Pr[n,i] + (-Qi[n,j])*Pi[n,i]
// GEMM D[128x64] = A[128x64] @ B[64x64]^T, A=[Qr|-Qi] precomputed to regs,
// B=[Pr|Pi] staged hi+lo interleaved 16B entries -> one LDS.128 per (nt,kk).
// 3 error-split passes: AhBh + AlBh + AhBl (fp32 acc).
// R13: 256 threads, 2-D warp grid (wm x wn = 4 x 2): warp owns rows wm*32,
// cols nt in [4wn, 4wn+4). Same total traffic, HALF the per-warp critical path
// (GEMM 96 MMAs/warp, staging 8 rows/warp, 16 STGs/warp) -> better phase overlap.

#define HH     1024
#define NHALF  32
#define LLEN   8192
#define TPB    256

#define Z0PITCH  36                   // float2 units; bank spread for (g,tig) gather
// dynamic smem byte offsets
#define TAB_W0   0                    // [8][32]  float2
#define TAB_W1   2048                 // [8][32]  float2 (S0c folded in)
#define TAB_Z0   4096                 // [16][Z0PITCH] float2 = 4608 B
#define TAB_Z1   8704                 // [8][32]  float2
#define SM_B     10752                // 64 rows x 320B  (16B entry [i][kk][tig])
#define BROWS    320                  // stride/16 = 20 ≡ 4 (mod 8) -> conflict-free LDS.128
#define SM_TOTAL (SM_B + 64 * BROWS)  // 31232

static __device__ __forceinline__ uint32_t pack_bf(float lo, float hi) {
    uint32_t r;
    asm("cvt.rn.bf16x2.f32 %0, %1, %2;" : "=r"(r) : "f"(hi), "f"(lo));
    return r;
}
static __device__ __forceinline__ void mma16816(float* c, const uint32_t* a,
                                                uint32_t b0, uint32_t b1) {
    asm volatile(
        "mma.sync.aligned.m16n8k16.row.col.f32.bf16.bf16.f32 "
        "{%0,%1,%2,%3}, {%4,%5,%6,%7}, {%8,%9}, {%0,%1,%2,%3};"
        : "+f"(c[0]), "+f"(c[1]), "+f"(c[2]), "+f"(c[3])
        : "r"(a[0]), "r"(a[1]), "r"(a[2]), "r"(a[3]), "r"(b0), "r"(b1));
}

// fp32 Cody-Waite: reduce (daif*mm) mod 2pi. k*F1 exact (k<2^14, F1 has 9 bits).
#define F1_C     6.28125f
#define F2_C     ((float)(6.283185307179586476925286766559 - (double)6.28125f))
#define F3_C     ((float)(6.283185307179586476925286766559 - (double)6.28125f \
                          - (double)((float)(6.283185307179586476925286766559 - (double)6.28125f))))
#define INV2PI_C 0.15915494309189533f

static __device__ __forceinline__ float reduce_phase(float daif, float mmf) {
    float hi = daif * mmf;
    float lo = fmaf(daif, mmf, -hi);           // exact residual
    float k  = rintf(hi * INV2PI_C);
    float r  = fmaf(-k, F1_C, hi);
    r = fmaf(-k, F2_C, r);
    r = fmaf(-k, F3_C, r);
    return r + lo;
}

// exp(dtA * mm) in fp32 with reduced phase
static __device__ __forceinline__ float2 cexp_dta(float darf, float daif, float mmf) {
    float r = reduce_phase(daif, mmf);
    float s, c;
    __sincosf(r, &s, &c);
    float mg = __expf(darf * mmf);
    return make_float2(mg * c, mg * s);
}

__global__ __launch_bounds__(TPB, 2)
void s4d_kernel(const float* __restrict__ C,
                const float* __restrict__ log_dt,
                const float* __restrict__ log_A_real,
                const float* __restrict__ A_imag,
                float* __restrict__ out)
{
    extern __shared__ char smem[];
    const int h   = blockIdx.x;
    const int t   = threadIdx.x;
    const int wid = t >> 5;
    const int lid = t & 31;
    const int n   = lid;
    const int wm  = wid & 3;          // row group: rows wm*32 .. +31
    const int wn  = wid >> 2;         // col group: nt in [4*wn, 4*wn+4)

    // ---- per-mode params (fp32, matches reference rounding) ----
    const float dt   = __expf(log_dt[h]);
    const float Arf  = -__expf(log_A_real[h * NHALF + n]);
    const float Ai   = A_imag[h * NHALF + n];
    const float darf = Arf * dt;
    const float daif = Ai * dt;

    // ---- incremental table build: warps 0-4 (others wait) ----
    if (wid < 5) {
        float2 seed = make_float2(1.0f, 0.0f);
        if (wid == 1) {  // fold S0c = 2*C*(exp(dtA)-1)/A into W1
            float2 e1 = cexp_dta(darf, daif, 1.0f);
            float cr = e1.x - 1.0f, ci = e1.y;
            float inv = __frcp_rn(Arf * Arf + Ai * Ai);
            float qr = (cr * Arf + ci * Ai) * inv;
            float qi = (ci * Arf - cr * Ai) * inv;
            float Cr = C[(h * NHALF + n) * 2 + 0];
            float Ci = C[(h * NHALF + n) * 2 + 1];
            seed = make_float2(2.0f * (Cr * qr - Ci * qi),
                               2.0f * (Cr * qi + Ci * qr));
        }
        int mul, ebase, taboff, stride;
        if      (wid == 0) { mul = 1;    ebase = 0; taboff = TAB_W0; stride = 32; }
        else if (wid == 1) { mul = 8;    ebase = 0; taboff = TAB_W1; stride = 32; }
        else if (wid == 2) { mul = 64;   ebase = 0; taboff = TAB_Z0; stride = Z0PITCH; }
        else if (wid == 3) { mul = 64;   ebase = 8; taboff = TAB_Z0; stride = Z0PITCH; }
        else               { mul = 1024; ebase = 0; taboff = TAB_Z1; stride = 32; }

        float2 base = cexp_dta(darf, daif, (float)mul);
        float2 cur;
        if (ebase == 0) cur = seed;     // e=0: w^0 (or S0c for W1)
        else            cur = cexp_dta(darf, daif, (float)(8 * mul));

        float2* tab = (float2*)(smem + taboff);
        tab[ebase * stride + n] = cur;
#pragma unroll
        for (int e2 = 1; e2 < 8; ++e2) {
            float nr = cur.x * base.x - cur.y * base.y;
            float ni = cur.x * base.y + cur.y * base.x;
            cur = make_float2(nr, ni);
            tab[(ebase + e2) * stride + n] = cur;
        }
    }
    __syncthreads();

    // ---- stage B: entry16[i][kk][tig] = {bhi(n0), blo(n0), bhi(n1), blo(n1)} ----
    // warp w -> rows w*8 .. +7; thread (mode n) writes the 8B half for its n:
    //   kk = n>>3, tig = n&3, half = (n>>2)&1
    {
        const float2* W0 = (const float2*)(smem + TAB_W0);
        const float2* W1 = (const float2*)(smem + TAB_W1);
        const uint32_t eoff = (uint32_t)((n >> 3) * 64 + (n & 3) * 16 + ((n >> 2) & 1) * 8);
#pragma unroll
        for (int r = 0; r < 8; ++r) {
            int i = wid * 8 + r;
            float2 w1 = W1[(i >> 3) * 32 + n];
            float2 w0 = W0[(i & 7) * 32 + n];
            float pr = w1.x * w0.x - w1.y * w0.y;
            float pi = w1.x * w0.y + w1.y * w0.x;
            uint32_t hp = pack_bf(pr, pi);
            float h0 = __uint_as_float(hp << 16);
            float h1 = __uint_as_float(hp & 0xFFFF0000u);
            uint32_t lp = pack_bf(pr - h0, pi - h1);
            *(uint2*)(smem + SM_B + (uint32_t)i * BROWS + eoff) = make_uint2(hp, lp);
        }
    }
    __syncthreads();

    // ---- precompute A fragments for all kk, both m-tiles of this wm ----
    const int g   = lid >> 2;
    const int tig = lid & 3;
    const float2* Z0p = (const float2*)(smem + TAB_Z0);
    const float2* Z1p = (const float2*)(smem + TAB_Z1);

    uint32_t Ah[4][2][4], Al[4][2][4];
#pragma unroll
    for (int kk = 0; kk < 4; ++kk) {
        const int n0 = kk * 8 + tig, n1 = n0 + 4;
        float2 za = Z0p[g * Z0PITCH + n0];
        float2 zb = Z0p[g * Z0PITCH + n1];
        float2 zc = Z0p[(g + 8) * Z0PITCH + n0];
        float2 zd = Z0p[(g + 8) * Z0PITCH + n1];
#pragma unroll
        for (int mt = 0; mt < 2; ++mt) {
            float2 zh0 = Z1p[(wm * 2 + mt) * 32 + n0];
            float2 zh1 = Z1p[(wm * 2 + mt) * 32 + n1];
            float vr[4], vi[4];
            vr[0] = zh0.x * za.x - zh0.y * za.y;  vi[0] = -(zh0.x * za.y + zh0.y * za.x);
            vr[1] = zh0.x * zc.x - zh0.y * zc.y;  vi[1] = -(zh0.x * zc.y + zh0.y * zc.x);
            vr[2] = zh1.x * zb.x - zh1.y * zb.y;  vi[2] = -(zh1.x * zb.y + zh1.y * zb.x);
            vr[3] = zh1.x * zd.x - zh1.y * zd.y;  vi[3] = -(zh1.x * zd.y + zh1.y * zd.x);
#pragma unroll
            for (int q = 0; q < 4; ++q) {
                uint32_t hp = pack_bf(vr[q], vi[q]);
                float h0 = __uint_as_float(hp << 16);
                float h1 = __uint_as_float(hp & 0xFFFF0000u);
                Ah[kk][mt][q] = hp;
                Al[kk][mt][q] = pack_bf(vr[q] - h0, vi[q] - h1);
            }
        }
    }

    // ---- GEMM, nt-outer over this warp's 4 nt values ----
    float* bp = out + (size_t)h * LLEN;
    const int j0 = wm * 32 + g;

#pragma unroll
    for (int nq = 0; nq < 4; ++nq) {
        const int nt = wn * 4 + nq;
        float acc0[4] = {0.f, 0.f, 0.f, 0.f};
        float acc1[4] = {0.f, 0.f, 0.f, 0.f};
        const char* brow = smem + SM_B + (uint32_t)(nt * 8 + g) * BROWS + tig * 16;
#pragma unroll
        for (int kk = 0; kk < 4; ++kk) {
            uint4 bv = *(const uint4*)(brow + kk * 64);   // {b0, l0, b1, l1}
            mma16816(acc0, Ah[kk][0], bv.x, bv.z);
            mma16816(acc1, Ah[kk][1], bv.x, bv.z);
            mma16816(acc0, Al[kk][0], bv.x, bv.z);
            mma16816(acc1, Al[kk][1], bv.x, bv.z);
            mma16816(acc0, Ah[kk][0], bv.y, bv.w);
            mma16816(acc1, Ah[kk][1], bv.y, bv.w);
        }
        const int col = nt * 8 + 2 * tig;
        *(float2*)(bp + (size_t)j0 * 64 + col)        = make_float2(acc0[0], acc0[1]);
        *(float2*)(bp + (size_t)(j0 + 8) * 64 + col)  = make_float2(acc0[2], acc0[3]);
        *(float2*)(bp + (size_t)(j0 + 16) * 64 + col) = make_float2(acc1[0], acc1[1]);
        *(float2*)(bp + (size_t)(j0 + 24) * 64 + col) = make_float2(acc1[2], acc1[3]);
    }
}

extern "C" void kernel_launch(void* const* d_in, const int* in_sizes, int n_in,
                              void* d_out, int out_size) {
    (void)in_sizes; (void)n_in; (void)out_size;
    const float* C          = (const float*)d_in[0];
    const float* log_dt     = (const float*)d_in[1];
    const float* log_A_real = (const float*)d_in[2];
    const float* A_imag     = (const float*)d_in[3];
    float* out = (float*)d_out;
    s4d_kernel<<<HH, TPB, SM_TOTAL>>>(C, log_dt, log_A_real, A_imag, out);
}

// round 14
// speedup vs baseline: 2.1058x; 2.1058x over previous
#include <cuda_runtime.h>
#include <cuda_fp16.h>
#include <cstdint>

// S4D kernel materialization via fp16 mma.sync (HMMA), all-fp32 setup.
//   K[h, l] = Re( sum_n S0c[h,n] * w^l ),  w = exp(dtA),  S0c = 2*C*(exp(dtA)-1)/A
// l = i + 64*j:  D[j,i] = sum_n Qr[n,j]*Pr[n,i] + (-Qi[n,j])*Pi[n,i]
// GEMM D[128x64] = A[128x64] @ B[64x64]^T, A=[Qr|-Qi] fp16 (single precision level,
// 11-bit mantissa), B=[Pr|Pi] fp16 hi+lo error-split staged as 16B entries.
// TWO passes: D = Ah*Bh + Ah*Bl (fp32 acc). Error ~2^-12 ~ 1e-4 << 1e-3 gate.
// Structure = R12 best: nt-outer GEMM, A-frags precomputed, Z0 pitch 36 (bank-safe).

#define HH     1024
#define NHALF  32
#define LLEN   8192
#define TPB    128

#define Z0PITCH  36                   // float2 units; bank spread for (g,tig) gather
// dynamic smem byte offsets
#define TAB_W0   0                    // [8][32]  float2
#define TAB_W1   2048                 // [8][32]  float2 (S0c folded in)
#define TAB_Z0   4096                 // [16][Z0PITCH] float2 = 4608 B
#define TAB_Z1   8704                 // [8][32]  float2
#define SM_B     10752                // 64 rows x 320B  (16B entry [i][kk][tig])
#define BROWS    320                  // stride/16 = 20 ≡ 4 (mod 8) -> conflict-free LDS.128
#define SM_TOTAL (SM_B + 64 * BROWS)  // 31232

static __device__ __forceinline__ uint32_t pack_h(float lo, float hi) {
    uint32_t r;
    asm("cvt.rn.f16x2.f32 %0, %1, %2;" : "=r"(r) : "f"(hi), "f"(lo));
    return r;
}
static __device__ __forceinline__ void mma16816(float* c, const uint32_t* a,
                                                uint32_t b0, uint32_t b1) {
    asm volatile(
        "mma.sync.aligned.m16n8k16.row.col.f32.f16.f16.f32 "
        "{%0,%1,%2,%3}, {%4,%5,%6,%7}, {%8,%9}, {%0,%1,%2,%3};"
        : "+f"(c[0]), "+f"(c[1]), "+f"(c[2]), "+f"(c[3])
        : "r"(a[0]), "r"(a[1]), "r"(a[2]), "r"(a[3]), "r"(b0), "r"(b1));
}

// fp32 Cody-Waite: reduce (daif*mm) mod 2pi. k*F1 exact (k<2^14, F1 has 9 bits).
#define F1_C     6.28125f
#define F2_C     ((float)(6.283185307179586476925286766559 - (double)6.28125f))
#define F3_C     ((float)(6.283185307179586476925286766559 - (double)6.28125f \
                          - (double)((float)(6.283185307179586476925286766559 - (double)6.28125f))))
#define INV2PI_C 0.15915494309189533f

static __device__ __forceinline__ float reduce_phase(float daif, float mmf) {
    float hi = daif * mmf;
    float lo = fmaf(daif, mmf, -hi);           // exact residual
    float k  = rintf(hi * INV2PI_C);
    float r  = fmaf(-k, F1_C, hi);
    r = fmaf(-k, F2_C, r);
    r = fmaf(-k, F3_C, r);
    return r + lo;
}

// exp(dtA * mm) in fp32 with reduced phase
static __device__ __forceinline__ float2 cexp_dta(float darf, float daif, float mmf) {
    float r = reduce_phase(daif, mmf);
    float s, c;
    __sincosf(r, &s, &c);
    float mg = __expf(darf * mmf);
    return make_float2(mg * c, mg * s);
}

__global__ __launch_bounds__(TPB, 5)
void s4d_kernel(const float* __restrict__ C,
                const float* __restrict__ log_dt,
                const float* __restrict__ log_A_real,
                const float* __restrict__ A_imag,
                float* __restrict__ out)
{
    extern __shared__ char smem[];
    const int h   = blockIdx.x;
    const int t   = threadIdx.x;
    const int wid = t >> 5;
    const int lid = t & 31;
    const int n   = lid;

    // ---- per-mode params (fp32, matches reference rounding) ----
    const float dt   = __expf(log_dt[h]);
    const float Arf  = -__expf(log_A_real[h * NHALF + n]);
    const float Ai   = A_imag[h * NHALF + n];
    const float darf = Arf * dt;
    const float daif = Ai * dt;

    // ---- incremental table build: 1 direct eval + 7 dependent cmuls ----
    {
        float2 seed = make_float2(1.0f, 0.0f);
        if (wid == 1) {  // fold S0c = 2*C*(exp(dtA)-1)/A into W1
            float2 e1 = cexp_dta(darf, daif, 1.0f);
            float cr = e1.x - 1.0f, ci = e1.y;
            float inv = __frcp_rn(Arf * Arf + Ai * Ai);
            float qr = (cr * Arf + ci * Ai) * inv;
            float qi = (ci * Arf - cr * Ai) * inv;
            float Cr = C[(h * NHALF + n) * 2 + 0];
            float Ci = C[(h * NHALF + n) * 2 + 1];
            seed = make_float2(2.0f * (Cr * qr - Ci * qi),
                               2.0f * (Cr * qi + Ci * qr));
        }
        int nt_tasks = (wid == 0) ? 2 : 1;
        for (int task = 0; task < nt_tasks; ++task) {
            int mul, ebase, taboff, stride;
            if (wid == 0) {
                if (task == 0) { mul = 1;    ebase = 0; taboff = TAB_W0; stride = 32; }
                else           { mul = 1024; ebase = 0; taboff = TAB_Z1; stride = 32; }
            }
            else if (wid == 1) { mul = 8;  ebase = 0; taboff = TAB_W1; stride = 32; }
            else if (wid == 2) { mul = 64; ebase = 0; taboff = TAB_Z0; stride = Z0PITCH; }
            else               { mul = 64; ebase = 8; taboff = TAB_Z0; stride = Z0PITCH; }

            float2 base = cexp_dta(darf, daif, (float)mul);
            float2 cur;
            if (ebase == 0) cur = seed;     // e=0: w^0 (or S0c for W1)
            else            cur = cexp_dta(darf, daif, (float)(8 * mul));

            float2* tab = (float2*)(smem + taboff);
            tab[ebase * stride + n] = cur;
#pragma unroll
            for (int e2 = 1; e2 < 8; ++e2) {
                float nr = cur.x * base.x - cur.y * base.y;
                float ni = cur.x * base.y + cur.y * base.x;
                cur = make_float2(nr, ni);
                tab[(ebase + e2) * stride + n] = cur;
            }
        }
    }
    __syncthreads();

    // ---- stage B: entry16[i][kk][tig] = {bh(n0), bl(n0), bh(n1), bl(n1)} ----
    // fp16 hi + residual-lo. Thread (mode n) writes its 8B half:
    //   kk = n>>3, tig = n&3, half = (n>>2)&1
    {
        const float2* W0 = (const float2*)(smem + TAB_W0);
        const float2* W1 = (const float2*)(smem + TAB_W1);
        const uint32_t eoff = (uint32_t)((n >> 3) * 64 + (n & 3) * 16 + ((n >> 2) & 1) * 8);
#pragma unroll
        for (int r = 0; r < 16; ++r) {
            int i = wid * 16 + r;
            float2 w1 = W1[(i >> 3) * 32 + n];
            float2 w0 = W0[(i & 7) * 32 + n];
            float pr = w1.x * w0.x - w1.y * w0.y;
            float pi = w1.x * w0.y + w1.y * w0.x;
            uint32_t hp = pack_h(pr, pi);
            float2 hf = __half22float2(*(__half2*)&hp);
            uint32_t lp = pack_h(pr - hf.x, pi - hf.y);
            *(uint2*)(smem + SM_B + (uint32_t)i * BROWS + eoff) = make_uint2(hp, lp);
        }
    }
    __syncthreads();

    // ---- precompute A fragments (fp16 hi only) for all kk, both m-tiles ----
    const int g   = lid >> 2;
    const int tig = lid & 3;
    const float2* Z0p = (const float2*)(smem + TAB_Z0);
    const float2* Z1p = (const float2*)(smem + TAB_Z1);

    uint32_t Ah[4][2][4];
#pragma unroll
    for (int kk = 0; kk < 4; ++kk) {
        const int n0 = kk * 8 + tig, n1 = n0 + 4;
        float2 za = Z0p[g * Z0PITCH + n0];
        float2 zb = Z0p[g * Z0PITCH + n1];
        float2 zc = Z0p[(g + 8) * Z0PITCH + n0];
        float2 zd = Z0p[(g + 8) * Z0PITCH + n1];
#pragma unroll
        for (int mt = 0; mt < 2; ++mt) {
            float2 zh0 = Z1p[(wid * 2 + mt) * 32 + n0];
            float2 zh1 = Z1p[(wid * 2 + mt) * 32 + n1];
            Ah[kk][mt][0] = pack_h(zh0.x * za.x - zh0.y * za.y,
                                   -(zh0.x * za.y + zh0.y * za.x));
            Ah[kk][mt][1] = pack_h(zh0.x * zc.x - zh0.y * zc.y,
                                   -(zh0.x * zc.y + zh0.y * zc.x));
            Ah[kk][mt][2] = pack_h(zh1.x * zb.x - zh1.y * zb.y,
                                   -(zh1.x * zb.y + zh1.y * zb.x));
            Ah[kk][mt][3] = pack_h(zh1.x * zd.x - zh1.y * zd.y,
                                   -(zh1.x * zd.y + zh1.y * zd.x));
        }
    }

    // ---- GEMM, nt-outer: one LDS.128 per (nt,kk); 2 passes: Ah*Bh + Ah*Bl ----
    float* bp = out + (size_t)h * LLEN;
    const int j0 = wid * 32 + g;

#pragma unroll
    for (int nt = 0; nt < 8; ++nt) {
        float acc0[4] = {0.f, 0.f, 0.f, 0.f};
        float acc1[4] = {0.f, 0.f, 0.f, 0.f};
        const char* brow = smem + SM_B + (uint32_t)(nt * 8 + g) * BROWS + tig * 16;
#pragma unroll
        for (int kk = 0; kk < 4; ++kk) {
            uint4 bv = *(const uint4*)(brow + kk * 64);   // {bh0, bl0, bh1, bl1}
            mma16816(acc0, Ah[kk][0], bv.x, bv.z);
            mma16816(acc1, Ah[kk][1], bv.x, bv.z);
            mma16816(acc0, Ah[kk][0], bv.y, bv.w);
            mma16816(acc1, Ah[kk][1], bv.y, bv.w);
        }
        const int col = nt * 8 + 2 * tig;
        *(float2*)(bp + (size_t)j0 * 64 + col)        = make_float2(acc0[0], acc0[1]);
        *(float2*)(bp + (size_t)(j0 + 8) * 64 + col)  = make_float2(acc0[2], acc0[3]);
        *(float2*)(bp + (size_t)(j0 + 16) * 64 + col) = make_float2(acc1[0], acc1[1]);
        *(float2*)(bp + (size_t)(j0 + 24) * 64 + col) = make_float2(acc1[2], acc1[3]);
    }
}

extern "C" void kernel_launch(void* const* d_in, const int* in_sizes, int n_in,
                              void* d_out, int out_size) {
    (void)in_sizes; (void)n_in; (void)out_size;
    const float* C          = (const float*)d_in[0];
    const float* log_dt     = (const float*)d_in[1];
    const float* log_A_real = (const float*)d_in[2];
    const float* A_imag     = (const float*)d_in[3];
    float* out = (float*)d_out;
    s4d_kernel<<<HH, TPB, SM_TOTAL>>>(C, log_dt, log_A_real, A_imag, out);
}